// round 15
// baseline (speedup 1.0000x reference)
#include <cuda_runtime.h>

// DotAttention: rnn_out [S,B,H] f32, state [2,2,B,H/2] f32 -> out [B,H,1] f32
// S=2048, B=32, H=1024.
// pass1: EXACT R7 shape: one warp per (b, 32-row chunk), 256-thr CTAs,
//        register mrg, CTA combine -> 256 partials. launch_dependents after
//        the mainloop.
// pass2: one g_acc load per thread (256 CTAs x 256 thr), weight computation
//        BEFORE griddepcontrol.wait so it overlaps pass1's epilogue (PDL).

#define S_LEN 2048
#define B_DIM 32
#define H_DIM 1024
#define SPLIT 64
#define CHUNK (S_LEN / SPLIT)          // 32 rows per warp
#define WARPS_PER_CTA 8
#define NCTA  (B_DIM * SPLIT / WARPS_PER_CTA)   // 256 CTAs
#define PPB   (SPLIT / WARPS_PER_CTA)           // 8 partials per batch

__device__ float g_m[NCTA];
__device__ float g_l[NCTA];
__device__ float g_acc[(size_t)NCTA * H_DIM];   // 1 MB scratch (L2-resident)

__global__ __launch_bounds__(256) void pass1(const float* __restrict__ rnn,
                                             const float* __restrict__ state) {
    const int tid  = threadIdx.x;
    const int lane = tid & 31;
    const int wid  = tid >> 5;
    const int warp  = blockIdx.x * WARPS_PER_CTA + wid;
    const int b     = warp / SPLIT;
    const int chunk = warp % SPLIT;

    // merged[b, h]: h = j*128 + lane*4; direction = h>>9
    float4 mrg[8];
#pragma unroll
    for (int j = 0; j < 8; j++) {
        int h = j * 128 + lane * 4;
        int d = h >> 9;
        int hh = h & 511;
        mrg[j] = *reinterpret_cast<const float4*>(
            state + (size_t)(2 + d) * B_DIM * 512 + (size_t)b * 512 + hh);
    }

    float4 acc[8];
#pragma unroll
    for (int j = 0; j < 8; j++) acc[j] = make_float4(0.f, 0.f, 0.f, 0.f);
    float m = -1e30f, l = 0.f;

    const float* base = rnn + (size_t)(chunk * CHUNK) * (B_DIM * H_DIM)
                            + (size_t)b * H_DIM;

    for (int s = 0; s < CHUNK; s++) {
        const float4* row =
            reinterpret_cast<const float4*>(base + (size_t)s * (B_DIM * H_DIM));
        float4 x[8];
#pragma unroll
        for (int j = 0; j < 8; j++) x[j] = row[j * 32 + lane];

        float p = 0.f;
#pragma unroll
        for (int j = 0; j < 8; j++) {
            p += x[j].x * mrg[j].x + x[j].y * mrg[j].y +
                 x[j].z * mrg[j].z + x[j].w * mrg[j].w;
        }
#pragma unroll
        for (int off = 16; off > 0; off >>= 1)
            p += __shfl_xor_sync(0xffffffffu, p, off);

        float mnew  = fmaxf(m, p);
        float scale = __expf(m - mnew);
        float w     = __expf(p - mnew);
#pragma unroll
        for (int j = 0; j < 8; j++) {
            acc[j].x = acc[j].x * scale + w * x[j].x;
            acc[j].y = acc[j].y * scale + w * x[j].y;
            acc[j].z = acc[j].z * scale + w * x[j].z;
            acc[j].w = acc[j].w * scale + w * x[j].w;
        }
        l = l * scale + w;
        m = mnew;
    }

    // mainloop done -> let pass2 start its prologue
    asm volatile("griddepcontrol.launch_dependents;");

    // ---- CTA-level combine of the 8 warps' partials ----
    __shared__ float s_m[WARPS_PER_CTA], s_l[WARPS_PER_CTA];
    __shared__ float4 sbuf[WARPS_PER_CTA][256];   // 32 KB

    if (lane == 0) { s_m[wid] = m; s_l[wid] = l; }
    __syncthreads();

    float M = s_m[0];
#pragma unroll
    for (int k = 1; k < WARPS_PER_CTA; k++) M = fmaxf(M, s_m[k]);
    float sc = __expf(m - M);

#pragma unroll
    for (int j = 0; j < 8; j++) {
        sbuf[wid][j * 32 + lane] =
            make_float4(acc[j].x * sc, acc[j].y * sc, acc[j].z * sc, acc[j].w * sc);
    }
    __syncthreads();

    // warp `wid` reduces j-group `wid` across the 8 staged buffers
    float4 r = make_float4(0.f, 0.f, 0.f, 0.f);
#pragma unroll
    for (int k = 0; k < WARPS_PER_CTA; k++) {
        float4 a = sbuf[k][wid * 32 + lane];
        r.x += a.x; r.y += a.y; r.z += a.z; r.w += a.w;
    }

    float4* out4 = reinterpret_cast<float4*>(g_acc + (size_t)blockIdx.x * H_DIM);
    out4[wid * 32 + lane] = r;

    if (tid == 0) {
        float L = 0.f;
#pragma unroll
        for (int k = 0; k < WARPS_PER_CTA; k++)
            L += s_l[k] * __expf(s_m[k] - M);
        g_m[blockIdx.x] = M;
        g_l[blockIdx.x] = L;
    }
}

// One g_acc load per thread. Weight prologue overlaps pass1 epilogue via PDL.
// NOTE: g_m/g_l are read AFTER griddepcontrol.wait (they're pass1 outputs);
// only the launch/setup cost overlaps.
__global__ __launch_bounds__(256) void pass2(float* __restrict__ out) {
    const int slice = blockIdx.x;        // 0..7 (128 h values each)
    const int b     = blockIdx.y;        // 0..31
    const int tid   = threadIdx.x;
    const int pos   = tid & 31;          // 32 float4 positions in slice
    const int k     = tid >> 5;          // 0..7 partial index

    asm volatile("griddepcontrol.wait;");   // pass1 fully complete

    float mv[PPB], lv[PPB];
#pragma unroll
    for (int j = 0; j < PPB; j++) {
        mv[j] = g_m[b * PPB + j];
        lv[j] = g_l[b * PPB + j];
    }
    float M = mv[0];
#pragma unroll
    for (int j = 1; j < PPB; j++) M = fmaxf(M, mv[j]);
    float L = 0.f;
#pragma unroll
    for (int j = 0; j < PPB; j++) L += lv[j] * __expf(mv[j] - M);
    float w   = __expf(mv[k] - M);
    float inv = 1.f / L;

    float4 a = *reinterpret_cast<const float4*>(
        g_acc + ((size_t)(b * PPB + k)) * H_DIM + slice * 128 + pos * 4);

    __shared__ float4 red[8][32];
    red[k][pos] = make_float4(w * a.x, w * a.y, w * a.z, w * a.w);
    __syncthreads();

#pragma unroll
    for (int st = 4; st > 0; st >>= 1) {
        if (k < st) {
            float4 o = red[k + st][pos];
            float4 c = red[k][pos];
            red[k][pos] = make_float4(c.x + o.x, c.y + o.y, c.z + o.z, c.w + o.w);
        }
        __syncthreads();
    }

    if (k == 0) {
        float4 c = red[0][pos];
        reinterpret_cast<float4*>(out)[(b * H_DIM + slice * 128) / 4 + pos] =
            make_float4(c.x * inv, c.y * inv, c.z * inv, c.w * inv);
    }
}

extern "C" void kernel_launch(void* const* d_in, const int* in_sizes, int n_in,
                              void* d_out, int out_size) {
    const float* rnn   = (const float*)d_in[0];
    const float* state = (const float*)d_in[1];
    float* out         = (float*)d_out;

    pass1<<<NCTA, 256>>>(rnn, state);

    cudaLaunchConfig_t cfg = {};
    cfg.gridDim  = dim3(8, B_DIM);
    cfg.blockDim = dim3(256);
    cudaLaunchAttribute attr[1];
    attr[0].id = cudaLaunchAttributeProgrammaticStreamSerialization;
    attr[0].val.programmaticStreamSerializationAllowed = 1;
    cfg.attrs = attr;
    cfg.numAttrs = 1;
    cudaLaunchKernelEx(&cfg, pass2, out);
}

// round 17
// speedup vs baseline: 1.0141x; 1.0141x over previous
#include <cuda_runtime.h>

// DotAttention: rnn_out [S,B,H] f32, state [2,2,B,H/2] f32 -> out [B,H,1] f32
// S=2048, B=32, H=1024.
// pass1: R7/R12 shape (best measured): one warp per (b, 32-row chunk),
//        256-thr CTAs, register mrg, CTA combine -> 256 partials.
//        rnn mainloop loads use __ldcs (evict-first: 268MB single-use stream,
//        keeps the 1MB g_acc scratch hot in L2 for pass2).
// pass2: R12 shape: 32 CTAs x 256 thr, 8 partials/batch, PDL launch.

#define S_LEN 2048
#define B_DIM 32
#define H_DIM 1024
#define SPLIT 64
#define CHUNK (S_LEN / SPLIT)          // 32 rows per warp
#define WARPS_PER_CTA 8
#define NCTA  (B_DIM * SPLIT / WARPS_PER_CTA)   // 256 CTAs
#define PPB   (SPLIT / WARPS_PER_CTA)           // 8 partials per batch

__device__ float g_m[NCTA];
__device__ float g_l[NCTA];
__device__ float g_acc[(size_t)NCTA * H_DIM];   // 1 MB scratch (L2-resident)

__global__ __launch_bounds__(256) void pass1(const float* __restrict__ rnn,
                                             const float* __restrict__ state) {
    const int tid  = threadIdx.x;
    const int lane = tid & 31;
    const int wid  = tid >> 5;
    const int warp  = blockIdx.x * WARPS_PER_CTA + wid;
    const int b     = warp / SPLIT;
    const int chunk = warp % SPLIT;

    // merged[b, h]: h = j*128 + lane*4; direction = h>>9
    float4 mrg[8];
#pragma unroll
    for (int j = 0; j < 8; j++) {
        int h = j * 128 + lane * 4;
        int d = h >> 9;
        int hh = h & 511;
        mrg[j] = *reinterpret_cast<const float4*>(
            state + (size_t)(2 + d) * B_DIM * 512 + (size_t)b * 512 + hh);
    }

    float4 acc[8];
#pragma unroll
    for (int j = 0; j < 8; j++) acc[j] = make_float4(0.f, 0.f, 0.f, 0.f);
    float m = -1e30f, l = 0.f;

    const float* base = rnn + (size_t)(chunk * CHUNK) * (B_DIM * H_DIM)
                            + (size_t)b * H_DIM;

    for (int s = 0; s < CHUNK; s++) {
        const float4* row =
            reinterpret_cast<const float4*>(base + (size_t)s * (B_DIM * H_DIM));
        float4 x[8];
#pragma unroll
        for (int j = 0; j < 8; j++) x[j] = __ldcs(&row[j * 32 + lane]);

        float p = 0.f;
#pragma unroll
        for (int j = 0; j < 8; j++) {
            p += x[j].x * mrg[j].x + x[j].y * mrg[j].y +
                 x[j].z * mrg[j].z + x[j].w * mrg[j].w;
        }
#pragma unroll
        for (int off = 16; off > 0; off >>= 1)
            p += __shfl_xor_sync(0xffffffffu, p, off);

        float mnew  = fmaxf(m, p);
        float scale = __expf(m - mnew);
        float w     = __expf(p - mnew);
#pragma unroll
        for (int j = 0; j < 8; j++) {
            acc[j].x = acc[j].x * scale + w * x[j].x;
            acc[j].y = acc[j].y * scale + w * x[j].y;
            acc[j].z = acc[j].z * scale + w * x[j].z;
            acc[j].w = acc[j].w * scale + w * x[j].w;
        }
        l = l * scale + w;
        m = mnew;
    }

    // mainloop done -> let pass2 start launching
    asm volatile("griddepcontrol.launch_dependents;");

    // ---- CTA-level combine of the 8 warps' partials ----
    __shared__ float s_m[WARPS_PER_CTA], s_l[WARPS_PER_CTA];
    __shared__ float4 sbuf[WARPS_PER_CTA][256];   // 32 KB

    if (lane == 0) { s_m[wid] = m; s_l[wid] = l; }
    __syncthreads();

    float M = s_m[0];
#pragma unroll
    for (int k = 1; k < WARPS_PER_CTA; k++) M = fmaxf(M, s_m[k]);
    float sc = __expf(m - M);

#pragma unroll
    for (int j = 0; j < 8; j++) {
        sbuf[wid][j * 32 + lane] =
            make_float4(acc[j].x * sc, acc[j].y * sc, acc[j].z * sc, acc[j].w * sc);
    }
    __syncthreads();

    // warp `wid` reduces j-group `wid` across the 8 staged buffers
    float4 r = make_float4(0.f, 0.f, 0.f, 0.f);
#pragma unroll
    for (int k = 0; k < WARPS_PER_CTA; k++) {
        float4 a = sbuf[k][wid * 32 + lane];
        r.x += a.x; r.y += a.y; r.z += a.z; r.w += a.w;
    }

    float4* out4 = reinterpret_cast<float4*>(g_acc + (size_t)blockIdx.x * H_DIM);
    out4[wid * 32 + lane] = r;

    if (tid == 0) {
        float L = 0.f;
#pragma unroll
        for (int k = 0; k < WARPS_PER_CTA; k++)
            L += s_l[k] * __expf(s_m[k] - M);
        g_m[blockIdx.x] = M;
        g_l[blockIdx.x] = L;
    }
}

// Combine + weighted sum over PPB=8 partials per batch. grid = 32 CTAs.
__global__ __launch_bounds__(256) void pass2(float* __restrict__ out) {
    const int b   = blockIdx.x;
    const int tid = threadIdx.x;         // owns one float4 (256*4 = 1024 = H)

    asm volatile("griddepcontrol.wait;");   // PDL: block until pass1 completes

    float mv[PPB], lv[PPB];
#pragma unroll
    for (int k = 0; k < PPB; k++) {
        mv[k] = g_m[b * PPB + k];
        lv[k] = g_l[b * PPB + k];
    }
    float M = mv[0];
#pragma unroll
    for (int k = 1; k < PPB; k++) M = fmaxf(M, mv[k]);
    float L = 0.f;
    float w[PPB];
#pragma unroll
    for (int k = 0; k < PPB; k++) {
        w[k] = __expf(mv[k] - M);
        L += lv[k] * w[k];
    }
    float inv = 1.f / L;

    const float* bse = g_acc + ((size_t)b * PPB) * H_DIM + tid * 4;
    float rx = 0.f, ry = 0.f, rz = 0.f, rw = 0.f;
#pragma unroll
    for (int k = 0; k < PPB; k++) {
        float4 a = *reinterpret_cast<const float4*>(bse + (size_t)k * H_DIM);
        rx += w[k] * a.x; ry += w[k] * a.y; rz += w[k] * a.z; rw += w[k] * a.w;
    }
    reinterpret_cast<float4*>(out)[b * (H_DIM / 4) + tid] =
        make_float4(rx * inv, ry * inv, rz * inv, rw * inv);
}

extern "C" void kernel_launch(void* const* d_in, const int* in_sizes, int n_in,
                              void* d_out, int out_size) {
    const float* rnn   = (const float*)d_in[0];
    const float* state = (const float*)d_in[1];
    float* out         = (float*)d_out;

    pass1<<<NCTA, 256>>>(rnn, state);

    cudaLaunchConfig_t cfg = {};
    cfg.gridDim  = dim3(B_DIM);
    cfg.blockDim = dim3(256);
    cudaLaunchAttribute attr[1];
    attr[0].id = cudaLaunchAttributeProgrammaticStreamSerialization;
    attr[0].val.programmaticStreamSerializationAllowed = 1;
    cfg.attrs = attr;
    cfg.numAttrs = 1;
    cudaLaunchKernelEx(&cfg, pass2, out);
}